// round 13
// baseline (speedup 1.0000x reference)
#include <cuda_runtime.h>
#include <cstdint>

#define BATCH 4
#define NPB   8192
#define HNPB  4096
#define MS    2048
#define KNB   64
#define NPTS  (BATCH*NPB)
#define CAP   1024
#define NB_FPS 8
#define NWORK 140
#define NSAMP (BATCH*MS)

typedef unsigned long long u64;

__device__ float  g_xw1[NPTS * 64];      // x @ W1[:64,:]
__device__ float  g_px[NPTS], g_py[NPTS], g_pz[NPTS];
__device__ float4 g_center[NSAMP];
__device__ int    g_prog[BATCH];
__device__ int    g_ready;
__device__ int    g_ticket;

// ---------- packed f32x2 helpers (bit-exact per-lane rn) ----------
__device__ __forceinline__ u64 pk2(float a, float b) {
    u64 r; asm("mov.b64 %0,{%1,%2};" : "=l"(r) : "f"(a), "f"(b)); return r;
}
__device__ __forceinline__ void upk2(u64 v, float& a, float& b) {
    asm("mov.b64 {%0,%1},%2;" : "=f"(a), "=f"(b) : "l"(v));
}
__device__ __forceinline__ u64 fma2(u64 a, u64 b, u64 c) {
    u64 d; asm("fma.rn.f32x2 %0,%1,%2,%3;" : "=l"(d) : "l"(a), "l"(b), "l"(c)); return d;
}
__device__ __forceinline__ u64 mul2(u64 a, u64 b) {
    u64 d; asm("mul.rn.f32x2 %0,%1,%2;" : "=l"(d) : "l"(a), "l"(b)); return d;
}
__device__ __forceinline__ u64 add2(u64 a, u64 b) {
    u64 d; asm("add.rn.f32x2 %0,%1,%2;" : "=l"(d) : "l"(a), "l"(b)); return d;
}
__device__ __forceinline__ void relu2(u64 a, float& f0, float& f1) {
    upk2(a, f0, f1);
    f0 = fmaxf(f0, 0.f); f1 = fmaxf(f1, 0.f);
}
// ---------- acquire/release scalar sync (global) ----------
__device__ __forceinline__ void st_rel(int* p, int v) {
    asm volatile("st.release.gpu.global.s32 [%0],%1;" :: "l"(p), "r"(v) : "memory");
}
__device__ __forceinline__ int ld_acq(const int* p) {
    int v; asm volatile("ld.acquire.gpu.global.s32 %0,[%1];" : "=r"(v) : "l"(p) : "memory");
    return v;
}
// ---------- cluster helpers ----------
__device__ __forceinline__ uint32_t smem_u32(const void* p) {
    uint32_t a;
    asm("{ .reg .u64 t; cvta.to.shared.u64 t, %1; cvt.u32.u64 %0, t; }" : "=r"(a) : "l"(p));
    return a;
}
__device__ __forceinline__ uint32_t ctarank() {
    uint32_t r; asm("mov.u32 %0, %%cluster_ctarank;" : "=r"(r)); return r;
}
__device__ __forceinline__ uint32_t mapa_u32(uint32_t addr, uint32_t rank) {
    uint32_t r; asm("mapa.shared::cluster.u32 %0, %1, %2;" : "=r"(r) : "r"(addr), "r"(rank));
    return r;
}
__device__ __forceinline__ void st_clu64(uint32_t addr, u64 v) {
    asm volatile("st.shared::cluster.b64 [%0], %1;" :: "r"(addr), "l"(v) : "memory");
}
// release-to-cluster flag store (orders the preceding st.shared::cluster msg words)
__device__ __forceinline__ void st_flag_release(uint32_t remote_addr, int v) {
    asm volatile("st.release.cluster.shared::cluster.u32 [%0], %1;" :: "r"(remote_addr), "r"(v) : "memory");
}
// acquire-from-cluster flag poll on own smem
__device__ __forceinline__ int ld_flag_acquire(uint32_t addr) {
    int v; asm volatile("ld.acquire.cluster.shared::cta.u32 %0, [%1];" : "=r"(v) : "r"(addr) : "memory");
    return v;
}

// ---------------- smem layout (bytes) ----------------
#define SA_W2   0
#define SA_W3   16384
#define SA_W1P  49152
#define SA_B1   49920
#define SA_B2   50176
#define SA_B3   50432
#define SA_H0   50944
#define SA_HSZ  26176            // cand 8192 + h1T 17408 + smax 512 + ctl 64
#define SMEM_TOTAL (SA_H0 + 2 * SA_HSZ)   // 103296
// fps role (per CTA: half cloud = 4096 points):
#define FP_PX   0
#define FP_PY   16384
#define FP_PZ   32768
#define FP_RED  49152            // swv [2][16] u32 (128) + swi [2][16] int (128)
#define FP_MSG  49408            // 2 slots x 32B (V|I, x|y, z)
#define FP_FLAG 49472            // 2 x u32 iteration flags

extern __shared__ char smem_raw[];

#define BARH asm volatile("bar.sync %0, %1;" :: "r"(1 + h), "r"(256) : "memory")

__global__ void reset_kernel() {
    int t = threadIdx.x;
    if (t < BATCH) g_prog[t] = 0;
    if (t == 4) g_ready = 0;
    if (t == 5) g_ticket = 0;
}

__global__ void __launch_bounds__(512, 1) mega_kernel(
    const float* __restrict__ pos, const float* __restrict__ x,
    const float* __restrict__ W1, const float* __restrict__ b1,
    const float* __restrict__ W2, const float* __restrict__ b2,
    const float* __restrict__ W3, const float* __restrict__ b3,
    float* __restrict__ out, int out_size) {

    const int bid = blockIdx.x;
    const int tid = threadIdx.x;

    if (bid < NB_FPS) {
        // ===== FPS: 2-CTA cluster per cloud, 4096 points per CTA =====
        const int b = bid >> 1;
        const uint32_t rank = ctarank();         // 0 or 1 within cluster
        const uint32_t peer = rank ^ 1u;
        float* spx = (float*)(smem_raw + FP_PX);
        float* spy = (float*)(smem_raw + FP_PY);
        float* spz = (float*)(smem_raw + FP_PZ);
        unsigned* swv = (unsigned*)(smem_raw + FP_RED);          // [2][16]
        int*      swi = (int*)(smem_raw + FP_RED + 128);         // [2][16]
        u64*      msg = (u64*)(smem_raw + FP_MSG);               // [2][4]
        int*      flg = (int*)(smem_raw + FP_FLAG);              // [2]
        const uint32_t smb = smem_u32(smem_raw);

        const float* pb = pos + (size_t)b * NPB * 3;
        const int base = (int)rank * HNPB;
        for (int i = tid; i < HNPB; i += 512) {
            spx[i] = pb[3 * (base + i)];
            spy[i] = pb[3 * (base + i) + 1];
            spz[i] = pb[3 * (base + i) + 2];
        }
        if (tid < 2) flg[tid] = 0;               // t starts at 1, 0 is safe init
        __syncthreads();
        // peer's flag init must be visible before any exchange
        asm volatile("barrier.cluster.arrive.aligned;" ::: "memory");
        asm volatile("barrier.cluster.wait.aligned;" ::: "memory");

        u64 X2[4], Y2[4], Z2[4];
        float md[8];
        #pragma unroll
        for (int g = 0; g < 4; g++) {
            int p0 = (2 * g) * 512 + tid, p1 = p0 + 512;
            X2[g] = pk2(spx[p0], spx[p1]);
            Y2[g] = pk2(spy[p0], spy[p1]);
            Z2[g] = pk2(spz[p0], spz[p1]);
            md[2 * g] = __int_as_float(0x7f800000);
            md[2 * g + 1] = __int_as_float(0x7f800000);
        }
        float sx = pb[0], sy = pb[1], sz = pb[2];   // sample 0 = point 0
        if (rank == 0 && tid == 0) {
            g_center[b * MS] = make_float4(sx, sy, sz, 0.f);
            st_rel(&g_prog[b], 1);
        }
        const int lane = tid & 31, wid = tid >> 5;

        for (int t = 1; t < MS; t++) {
            const int par = (t & 1) * 16;
            u64 nx = pk2(-sx, -sx), ny = pk2(-sy, -sy), nz = pk2(-sz, -sz);
            float tmax = -1.0f;
            #pragma unroll
            for (int g = 0; g < 4; g++) {
                // exact XLA fp32: rn sub (add of exact negation), rn muls, ((xx+yy)+zz)
                u64 dx = add2(X2[g], nx);
                u64 dy = add2(Y2[g], ny);
                u64 dz = add2(Z2[g], nz);
                u64 d2 = add2(add2(mul2(dx, dx), mul2(dy, dy)), mul2(dz, dz));
                float d0, d1; upk2(d2, d0, d1);
                float m0 = fminf(md[2 * g], d0);     md[2 * g] = m0;
                float m1 = fminf(md[2 * g + 1], d1); md[2 * g + 1] = m1;
                tmax = fmaxf(tmax, fmaxf(m0, m1));
            }
            unsigned vb = __float_as_uint(tmax);            // md >= 0: bits monotone
            unsigned Vw = __reduce_max_sync(0xffffffffu, vb);
            int loc = 0x7fffffff;
            if (vb == Vw) {                                  // round-8 shape: per-warp scan
                float Vf = __uint_as_float(Vw);
                #pragma unroll
                for (int g = 3; g >= 0; g--) {
                    if (md[2 * g + 1] == Vf) loc = (2 * g + 1) * 512 + tid;
                    if (md[2 * g]     == Vf) loc = (2 * g) * 512 + tid;
                }
            }
            unsigned Iw = __reduce_min_sync(0xffffffffu, (unsigned)loc);
            if (lane == 0) { swv[par + wid] = Vw; swi[par + wid] = (int)Iw; }
            __syncthreads();
            unsigned v  = (lane < 16) ? swv[par + lane] : 0u;
            unsigned i2 = (lane < 16) ? (unsigned)swi[par + lane] : 0x7fffffffu;
            unsigned Vg = __reduce_max_sync(0xffffffffu, v);
            unsigned Ig = __reduce_min_sync(0xffffffffu, (v == Vg) ? i2 : 0x7fffffffu);
            // local winner coords + global index
            float lx = spx[Ig], ly = spy[Ig], lz = spz[Ig];
            unsigned Iglob = (rank << 12) | Ig;              // rank*4096 + Ig

            // exchange with peer: slot = t&1, release-store msg+flag, acquire-poll own flag
            const int sl = t & 1;
            if (tid == 0) {
                uint32_t rm = mapa_u32(smb + FP_MSG + sl * 32, peer);
                st_clu64(rm,      ((u64)Iglob << 32) | (u64)Vg);
                st_clu64(rm + 8,  pk2(lx, ly));
                st_clu64(rm + 16, (u64)__float_as_uint(lz));
                st_flag_release(mapa_u32(smb + FP_FLAG + sl * 4, peer), t);
            }
            {
                uint32_t fa = smb + FP_FLAG + sl * 4;
                while (ld_flag_acquire(fa) != t) { }
            }
            u64 q0 = msg[sl * 4], q1 = msg[sl * 4 + 1], q2 = msg[sl * 4 + 2];
            unsigned Vp = (unsigned)q0, Ip = (unsigned)(q0 >> 32);
            bool peerWins = (Vp > Vg) || (Vp == Vg && Ip < Iglob);
            if (peerWins) {
                float qx, qy; upk2(q1, qx, qy);
                sx = qx; sy = qy; sz = __uint_as_float((unsigned)q2);
            } else {
                sx = lx; sy = ly; sz = lz;
            }
            if (rank == 0 && tid == 0) {
                g_center[b * MS + t] = make_float4(sx, sy, sz, 0.f);
                st_rel(&g_prog[b], t + 1);
            }
        }

    } else {
        // ======================= persistent workers: 2 halves of 256 =======================
        const int w = bid - NB_FPS;        // 0..139
        float* W2s  = (float*)(smem_raw + SA_W2);    // holds W1 during prologue
        float* W3s  = (float*)(smem_raw + SA_W3);
        float* W1ps = (float*)(smem_raw + SA_W1P);
        float* b1s  = (float*)(smem_raw + SA_B1);
        float* b2s  = (float*)(smem_raw + SA_B2);
        float* b3s  = (float*)(smem_raw + SA_B3);

        // ---- prologue 1: SoA transpose chunk ----
        for (int p = w * 512 + tid; p < NPTS; p += NWORK * 512) {
            g_px[p] = pos[3 * p]; g_py[p] = pos[3 * p + 1]; g_pz[p] = pos[3 * p + 2];
        }
        // ---- prologue 2: xw1 chunk (W1 staged where W2 will live) ----
        for (int i = tid; i < 4096; i += 512) W2s[i] = W1[i];
        __syncthreads();
        {
            float* xs = (float*)(smem_raw + SA_H0);
            int rl = tid >> 6, cc = tid & 63;
            for (int r0 = w * 8; r0 < NPTS; r0 += NWORK * 8) {
                xs[tid] = x[(size_t)r0 * 64 + tid];
                __syncthreads();
                float acc = 0.f;
                #pragma unroll
                for (int k = 0; k < 64; k++) acc = fmaf(xs[rl * 64 + k], W2s[k * 64 + cc], acc);
                g_xw1[(size_t)(r0 + rl) * 64 + cc] = acc;
                __syncthreads();
            }
        }
        __threadfence();          // order g_px/g_xw1 before ready signal
        __syncthreads();
        if (tid == 0) atomicAdd(&g_ready, 1);

        // ---- load MLP weights ----
        for (int i = tid; i < 4096; i += 512) W2s[i] = W2[i];
        for (int i = tid; i < 8192; i += 512) W3s[i] = W3[i];
        if (tid < 192) W1ps[tid] = W1[4096 + tid];
        if (tid < 64) { b1s[tid] = b1[tid]; b2s[tid] = b2[tid]; }
        if (tid < 128) b3s[tid] = b3[tid];
        __syncthreads();
        if (tid == 0) { while (ld_acq(&g_ready) < NWORK) __nanosleep(512); }
        __syncthreads();          // all producers done; g_px/g_xw1 globally visible

        // ---- halves: ticket loop ----
        const int h  = tid >> 8;
        const int t2 = tid & 255;
        char* hb = smem_raw + SA_H0 + h * SA_HSZ;
        u64*   cand = (u64*)hb;
        float* h1T  = (float*)(hb + 8192);       // reused as h2T after layer 2
        int*   smax = (int*)(hb + 25600);
        int*   ctl  = (int*)(hb + 26112);        // [0]=scnt [1]=ticket

        const float R2 = (float)(0.2 * 0.2);
        const int OUT1 = NSAMP * 128;
        const int OUT2 = OUT1 + NSAMP * 3;
        const int OUT3 = OUT2 + NSAMP;

        while (true) {
            if (t2 == 0) ctl[1] = atomicAdd(&g_ticket, 1);
            BARH;
            const int q = ctl[1];
            if (q >= NSAMP) break;
            const int c = q & 3, m = q >> 2;
            const int row = c * MS + m;
            const int g0 = c * NPB;

            for (int i = t2; i < CAP; i += 256) cand[i] = ~0ull;
            if (t2 < 128) smax[t2] = 0;
            if (t2 == 0) {
                ctl[0] = 0;
                while (ld_acq(&g_prog[c]) <= m) __nanosleep(256);   // single poller
            }
            BARH;
            float4 ctr = __ldcg((const float4*)&g_center[row]);
            const float cx = ctr.x, cy = ctr.y, cz = ctr.z;

            // radius scan, packed pairs (exact fp32 semantics)
            {
                const u64* px2 = (const u64*)(g_px + g0);
                const u64* py2 = (const u64*)(g_py + g0);
                const u64* pz2 = (const u64*)(g_pz + g0);
                const u64 ncx2 = pk2(-cx, -cx), ncy2 = pk2(-cy, -cy), ncz2 = pk2(-cz, -cz);
                for (int iq = t2; iq < NPB / 2; iq += 256) {
                    u64 dx2 = add2(px2[iq], ncx2);
                    u64 dy2 = add2(py2[iq], ncy2);
                    u64 dz2 = add2(pz2[iq], ncz2);
                    u64 d22 = add2(add2(mul2(dx2, dx2), mul2(dy2, dy2)), mul2(dz2, dz2));
                    float d0, d1; upk2(d22, d0, d1);
                    if (d0 <= R2) {
                        int sp = atomicAdd(ctl, 1);
                        if (sp < CAP) cand[sp] = ((u64)__float_as_uint(d0) << 32) | (unsigned)(2 * iq);
                    }
                    if (d1 <= R2) {
                        int sp = atomicAdd(ctl, 1);
                        if (sp < CAP) cand[sp] = ((u64)__float_as_uint(d1) << 32) | (unsigned)(2 * iq + 1);
                    }
                }
            }
            BARH;
            int n = ctl[0]; if (n > CAP) n = CAP;

            // bitonic sort over next-pow2(n) (u64 keys: d2 major, idx minor == lax.top_k ties)
            if (n > KNB) {
                int np2 = 128;
                while (np2 < n) np2 <<= 1;
                for (int k = 2; k <= np2; k <<= 1) {
                    for (int j = k >> 1; j > 0; j >>= 1) {
                        BARH;
                        for (int i = t2; i < np2; i += 256) {
                            int ixj = i ^ j;
                            if (ixj > i) {
                                u64 a = cand[i], cc2 = cand[ixj];
                                bool asc = ((i & k) == 0);
                                if ((a > cc2) == asc) { cand[i] = cc2; cand[ixj] = a; }
                            }
                        }
                    }
                }
            }
            BARH;
            const int nv = n < KNB ? n : KNB;

            // h1 = relu(X'[j] + relpos @ W1p + b1), transposed [col][n], stride 68
            for (int p = t2; p < 4096; p += 256) {
                int nn = p >> 6, ccol = p & 63;
                float v = 0.f;
                if (nn < nv) {
                    int j = (int)(unsigned)(cand[nn] & 0xffffffffull);
                    float rx = g_px[g0 + j] - cx;
                    float ry = g_py[g0 + j] - cy;
                    float rz = g_pz[g0 + j] - cz;
                    v = g_xw1[(size_t)(g0 + j) * 64 + ccol];
                    v = fmaf(rx, W1ps[ccol], v);
                    v = fmaf(ry, W1ps[64 + ccol], v);
                    v = fmaf(rz, W1ps[128 + ccol], v);
                    v = fmaxf(v + b1s[ccol], 0.f);
                }
                h1T[ccol * 68 + nn] = v;
            }
            BARH;

            // layer 2: h2 = relu(h1 @ W2 + b2); packed f32x2
            {
                int tn = t2 >> 4, tc = t2 & 15;
                ulonglong2 bb = *(const ulonglong2*)(b2s + tc * 4);
                u64 acc[4][2];
                #pragma unroll
                for (int i = 0; i < 4; i++) { acc[i][0] = bb.x; acc[i][1] = bb.y; }
                #pragma unroll 8
                for (int k = 0; k < 64; k++) {
                    float4 a = *(const float4*)(h1T + k * 68 + tn * 4);
                    ulonglong2 ww = *(const ulonglong2*)(W2s + k * 64 + tc * 4);
                    u64 a0 = pk2(a.x, a.x), a1 = pk2(a.y, a.y), a2 = pk2(a.z, a.z), a3 = pk2(a.w, a.w);
                    acc[0][0] = fma2(a0, ww.x, acc[0][0]); acc[0][1] = fma2(a0, ww.y, acc[0][1]);
                    acc[1][0] = fma2(a1, ww.x, acc[1][0]); acc[1][1] = fma2(a1, ww.y, acc[1][1]);
                    acc[2][0] = fma2(a2, ww.x, acc[2][0]); acc[2][1] = fma2(a2, ww.y, acc[2][1]);
                    acc[3][0] = fma2(a3, ww.x, acc[3][0]); acc[3][1] = fma2(a3, ww.y, acc[3][1]);
                }
                BARH;  // all reads of h1T done; reuse buffer for h2T
                #pragma unroll
                for (int i = 0; i < 4; i++)
                    #pragma unroll
                    for (int jp = 0; jp < 2; jp++) {
                        float f0, f1; relu2(acc[i][jp], f0, f1);
                        h1T[(tc * 4 + 2 * jp) * 68 + tn * 4 + i] = f0;
                        h1T[(tc * 4 + 2 * jp + 1) * 68 + tn * 4 + i] = f1;
                    }
                BARH;
            }

            // layer 3: relu(h2 @ W3 + b3) fused with maxpool
            {
                int tn = t2 >> 4, tc = t2 & 15;
                ulonglong2 bb0 = *(const ulonglong2*)(b3s + tc * 8);
                ulonglong2 bb1 = *(const ulonglong2*)(b3s + tc * 8 + 4);
                u64 acc[4][4];
                #pragma unroll
                for (int i = 0; i < 4; i++) {
                    acc[i][0] = bb0.x; acc[i][1] = bb0.y; acc[i][2] = bb1.x; acc[i][3] = bb1.y;
                }
                #pragma unroll 4
                for (int k = 0; k < 64; k++) {
                    float4 a = *(const float4*)(h1T + k * 68 + tn * 4);
                    ulonglong2 w0 = *(const ulonglong2*)(W3s + k * 128 + tc * 8);
                    ulonglong2 w1 = *(const ulonglong2*)(W3s + k * 128 + tc * 8 + 4);
                    u64 a0 = pk2(a.x, a.x), a1 = pk2(a.y, a.y), a2 = pk2(a.z, a.z), a3 = pk2(a.w, a.w);
                    acc[0][0] = fma2(a0, w0.x, acc[0][0]); acc[0][1] = fma2(a0, w0.y, acc[0][1]);
                    acc[0][2] = fma2(a0, w1.x, acc[0][2]); acc[0][3] = fma2(a0, w1.y, acc[0][3]);
                    acc[1][0] = fma2(a1, w0.x, acc[1][0]); acc[1][1] = fma2(a1, w0.y, acc[1][1]);
                    acc[1][2] = fma2(a1, w1.x, acc[1][2]); acc[1][3] = fma2(a1, w1.y, acc[1][3]);
                    acc[2][0] = fma2(a2, w0.x, acc[2][0]); acc[2][1] = fma2(a2, w0.y, acc[2][1]);
                    acc[2][2] = fma2(a2, w1.x, acc[2][2]); acc[2][3] = fma2(a2, w1.y, acc[2][3]);
                    acc[3][0] = fma2(a3, w0.x, acc[3][0]); acc[3][1] = fma2(a3, w0.y, acc[3][1]);
                    acc[3][2] = fma2(a3, w1.x, acc[3][2]); acc[3][3] = fma2(a3, w1.y, acc[3][3]);
                }
                if (tn * 4 < nv) {
                    int vr = nv - tn * 4; if (vr > 4) vr = 4;
                    #pragma unroll
                    for (int jp = 0; jp < 4; jp++) {
                        float m0 = 0.f, m1 = 0.f;
                        for (int i = 0; i < vr; i++) {
                            float f0, f1; relu2(acc[i][jp], f0, f1);
                            m0 = fmaxf(m0, f0); m1 = fmaxf(m1, f1);
                        }
                        atomicMax(&smax[tc * 8 + 2 * jp], __float_as_int(m0));   // nonneg: int order == float order
                        atomicMax(&smax[tc * 8 + 2 * jp + 1], __float_as_int(m1));
                    }
                }
                BARH;
            }

            // outputs: [B*M,128] feat, [B*M,3] pos, [B*M] batch
            if (t2 < 128) out[(size_t)row * 128 + t2] = __int_as_float(smax[t2]);
            if (out_size >= OUT2 && t2 == 128) {
                float* po = out + OUT1 + (size_t)row * 3;
                po[0] = cx; po[1] = cy; po[2] = cz;
            }
            if (out_size >= OUT3 && t2 == 129) out[OUT2 + row] = (float)c;
            BARH;   // protect cand/smax reset of next iteration
        }
    }
}

extern "C" void kernel_launch(void* const* d_in, const int* in_sizes, int n_in,
                              void* d_out, int out_size) {
    const float* x   = (const float*)d_in[0];
    const float* pos = (const float*)d_in[1];
    // d_in[2] = batch (implicit by layout)
    const float* W1 = (const float*)d_in[3];
    const float* b1 = (const float*)d_in[4];
    const float* W2 = (const float*)d_in[5];
    const float* b2 = (const float*)d_in[6];
    const float* W3 = (const float*)d_in[7];
    const float* b3 = (const float*)d_in[8];

    cudaFuncSetAttribute(mega_kernel, cudaFuncAttributeMaxDynamicSharedMemorySize, SMEM_TOTAL);

    reset_kernel<<<1, 32>>>();

    cudaLaunchConfig_t cfg = {};
    cfg.gridDim = dim3(NB_FPS + NWORK, 1, 1);   // 148 = 74 clusters of 2
    cfg.blockDim = dim3(512, 1, 1);
    cfg.dynamicSmemBytes = SMEM_TOTAL;
    cudaLaunchAttribute attrs[1];
    attrs[0].id = cudaLaunchAttributeClusterDimension;
    attrs[0].val.clusterDim = {2, 1, 1};
    cfg.attrs = attrs;
    cfg.numAttrs = 1;
    cudaLaunchKernelEx(&cfg, mega_kernel, pos, x, W1, b1, W2, b2, W3, b3,
                       (float*)d_out, out_size);
}

// round 14
// speedup vs baseline: 1.7829x; 1.7829x over previous
#include <cuda_runtime.h>

#define BATCH 4
#define NPB   8192
#define MS    2048
#define KNB   64
#define NPTS  (BATCH*NPB)
#define CAP   1024
#define NWORK 144
#define NSAMP (BATCH*MS)

typedef unsigned long long u64;

__device__ float  g_xw1[NPTS * 64];      // x @ W1[:64,:]
__device__ float  g_px[NPTS], g_py[NPTS], g_pz[NPTS];
__device__ float4 g_center[NSAMP];
__device__ int    g_prog[BATCH];
__device__ int    g_ready;
__device__ int    g_ticket;

// ---------- packed f32x2 helpers (bit-exact per-lane rn) ----------
__device__ __forceinline__ u64 pk2(float a, float b) {
    u64 r; asm("mov.b64 %0,{%1,%2};" : "=l"(r) : "f"(a), "f"(b)); return r;
}
__device__ __forceinline__ void upk2(u64 v, float& a, float& b) {
    asm("mov.b64 {%0,%1},%2;" : "=f"(a), "=f"(b) : "l"(v));
}
__device__ __forceinline__ u64 fma2(u64 a, u64 b, u64 c) {
    u64 d; asm("fma.rn.f32x2 %0,%1,%2,%3;" : "=l"(d) : "l"(a), "l"(b), "l"(c)); return d;
}
__device__ __forceinline__ u64 mul2(u64 a, u64 b) {
    u64 d; asm("mul.rn.f32x2 %0,%1,%2;" : "=l"(d) : "l"(a), "l"(b)); return d;
}
__device__ __forceinline__ u64 add2(u64 a, u64 b) {
    u64 d; asm("add.rn.f32x2 %0,%1,%2;" : "=l"(d) : "l"(a), "l"(b)); return d;
}
__device__ __forceinline__ void relu2(u64 a, float& f0, float& f1) {
    upk2(a, f0, f1);
    f0 = fmaxf(f0, 0.f); f1 = fmaxf(f1, 0.f);
}
// ---------- acquire/release scalar sync ----------
__device__ __forceinline__ void st_rel(int* p, int v) {
    asm volatile("st.release.gpu.global.s32 [%0],%1;" :: "l"(p), "r"(v) : "memory");
}
__device__ __forceinline__ int ld_acq(const int* p) {
    int v; asm volatile("ld.acquire.gpu.global.s32 %0,[%1];" : "=r"(v) : "l"(p) : "memory");
    return v;
}

// ---------------- smem layout (bytes) ----------------
#define SA_W2   0
#define SA_W3   16384
#define SA_W1P  49152
#define SA_B1   49920
#define SA_B2   50176
#define SA_B3   50432
#define SA_H0   50944
#define SA_HSZ  26176            // cand 8192 + h1T 17408 + smax 512 + ctl 64
#define SMEM_TOTAL (SA_H0 + 2 * SA_HSZ)   // 103296
// fps role:
#define FP_PX   0
#define FP_PY   32768
#define FP_PZ   65536
#define FP_RED  98304

extern __shared__ char smem_raw[];

#define BARH asm volatile("bar.sync %0, %1;" :: "r"(1 + h), "r"(256) : "memory")

__global__ void reset_kernel() {
    int t = threadIdx.x;
    if (t < BATCH) g_prog[t] = 0;
    if (t == 4) g_ready = 0;
    if (t == 5) g_ticket = 0;
}

__global__ void __launch_bounds__(512, 1) mega_kernel(
    const float* __restrict__ pos, const float* __restrict__ x,
    const float* __restrict__ W1, const float* __restrict__ b1,
    const float* __restrict__ W2, const float* __restrict__ b2,
    const float* __restrict__ W3, const float* __restrict__ b3,
    float* __restrict__ out, int out_size) {

    const int bid = blockIdx.x;
    const int tid = threadIdx.x;

    if (bid < BATCH) {
        // ======================= FPS: one SM per cloud, 16 warps =======================
        const int b = bid;
        float* spx = (float*)(smem_raw + FP_PX);
        float* spy = (float*)(smem_raw + FP_PY);
        float* spz = (float*)(smem_raw + FP_PZ);
        unsigned* swv = (unsigned*)(smem_raw + FP_RED);          // [2][16]
        int*      swi = (int*)(smem_raw + FP_RED + 128);         // [2][16]

        const float* pb = pos + (size_t)b * NPB * 3;
        for (int i = tid; i < NPB; i += 512) {
            spx[i] = pb[3 * i]; spy[i] = pb[3 * i + 1]; spz[i] = pb[3 * i + 2];
        }
        __syncthreads();

        u64 X2[8], Y2[8], Z2[8];
        float md[16];
        #pragma unroll
        for (int g = 0; g < 8; g++) {
            int p0 = (2 * g) * 512 + tid, p1 = p0 + 512;
            X2[g] = pk2(spx[p0], spx[p1]);
            Y2[g] = pk2(spy[p0], spy[p1]);
            Z2[g] = pk2(spz[p0], spz[p1]);
            md[2 * g] = __int_as_float(0x7f800000);
            md[2 * g + 1] = __int_as_float(0x7f800000);
        }
        float sx = spx[0], sy = spy[0], sz = spz[0];
        if (tid == 0) {
            g_center[b * MS] = make_float4(sx, sy, sz, 0.f);
            st_rel(&g_prog[b], 1);
        }
        const int lane = tid & 31, wid = tid >> 5;

        for (int t = 1; t < MS; t++) {
            u64 nx = pk2(-sx, -sx), ny = pk2(-sy, -sy), nz = pk2(-sz, -sz);
            float tmax = -1.0f;
            #pragma unroll
            for (int g = 0; g < 8; g++) {
                // exact XLA fp32: rn sub (add of exact negation), rn muls, ((xx+yy)+zz)
                u64 dx = add2(X2[g], nx);
                u64 dy = add2(Y2[g], ny);
                u64 dz = add2(Z2[g], nz);
                u64 d2 = add2(add2(mul2(dx, dx), mul2(dy, dy)), mul2(dz, dz));
                float d0, d1; upk2(d2, d0, d1);
                float m0 = fminf(md[2 * g], d0);     md[2 * g] = m0;
                float m1 = fminf(md[2 * g + 1], d1); md[2 * g + 1] = m1;
                tmax = fmaxf(tmax, fmaxf(m0, m1));
            }
            unsigned vb = __float_as_uint(tmax);            // md >= 0: bits monotone
            unsigned Vw = __reduce_max_sync(0xffffffffu, vb);
            // branchless first-index scan: lanes with vb < Vw match nothing -> loc stays MAX
            float Vf = __uint_as_float(Vw);
            int loc = 0x7fffffff;
            #pragma unroll
            for (int g = 7; g >= 0; g--) {
                if (md[2 * g + 1] == Vf) loc = (2 * g + 1) * 512 + tid;
                if (md[2 * g]     == Vf) loc = (2 * g) * 512 + tid;
            }
            unsigned Iw = __reduce_min_sync(0xffffffffu, (unsigned)loc);
            const int par = (t & 1) * 16;
            if (lane == 0) { swv[par + wid] = Vw; swi[par + wid] = (int)Iw; }
            __syncthreads();   // single barrier per iter; parity double-buffer bounds skew
            unsigned v  = (lane < 16) ? swv[par + lane] : 0u;
            unsigned i2 = (lane < 16) ? (unsigned)swi[par + lane] : 0x7fffffffu;
            unsigned Vg = __reduce_max_sync(0xffffffffu, v);
            unsigned Ig = __reduce_min_sync(0xffffffffu, (v == Vg) ? i2 : 0x7fffffffu);
            sx = spx[Ig]; sy = spy[Ig]; sz = spz[Ig];        // broadcast LDS
            if (tid == 0) {
                g_center[b * MS + t] = make_float4(sx, sy, sz, 0.f);
                st_rel(&g_prog[b], t + 1);
            }
        }

    } else {
        // ======================= persistent workers: 2 halves of 256 =======================
        const int w = bid - BATCH;        // 0..143
        float* W2s  = (float*)(smem_raw + SA_W2);    // holds W1 during prologue
        float* W3s  = (float*)(smem_raw + SA_W3);
        float* W1ps = (float*)(smem_raw + SA_W1P);
        float* b1s  = (float*)(smem_raw + SA_B1);
        float* b2s  = (float*)(smem_raw + SA_B2);
        float* b3s  = (float*)(smem_raw + SA_B3);

        // ---- prologue 1: SoA transpose chunk ----
        for (int p = w * 512 + tid; p < NPTS; p += NWORK * 512) {
            g_px[p] = pos[3 * p]; g_py[p] = pos[3 * p + 1]; g_pz[p] = pos[3 * p + 2];
        }
        // ---- prologue 2: xw1 chunk (W1 staged where W2 will live) ----
        for (int i = tid; i < 4096; i += 512) W2s[i] = W1[i];
        __syncthreads();
        {
            float* xs = (float*)(smem_raw + SA_H0);
            int rl = tid >> 6, cc = tid & 63;
            for (int r0 = w * 8; r0 < NPTS; r0 += NWORK * 8) {
                xs[tid] = x[(size_t)r0 * 64 + tid];
                __syncthreads();
                float acc = 0.f;
                #pragma unroll
                for (int k = 0; k < 64; k++) acc = fmaf(xs[rl * 64 + k], W2s[k * 64 + cc], acc);
                g_xw1[(size_t)(r0 + rl) * 64 + cc] = acc;
                __syncthreads();
            }
        }
        __threadfence();          // order g_px/g_xw1 before ready signal
        __syncthreads();
        if (tid == 0) atomicAdd(&g_ready, 1);

        // ---- load MLP weights ----
        for (int i = tid; i < 4096; i += 512) W2s[i] = W2[i];
        for (int i = tid; i < 8192; i += 512) W3s[i] = W3[i];
        if (tid < 192) W1ps[tid] = W1[4096 + tid];
        if (tid < 64) { b1s[tid] = b1[tid]; b2s[tid] = b2[tid]; }
        if (tid < 128) b3s[tid] = b3[tid];
        __syncthreads();
        if (tid == 0) { while (ld_acq(&g_ready) < NWORK) __nanosleep(512); }
        __syncthreads();          // all producers done; g_px/g_xw1 globally visible

        // ---- halves: ticket loop ----
        const int h  = tid >> 8;
        const int t2 = tid & 255;
        char* hb = smem_raw + SA_H0 + h * SA_HSZ;
        u64*   cand = (u64*)hb;
        float* h1T  = (float*)(hb + 8192);       // reused as h2T after layer 2
        int*   smax = (int*)(hb + 25600);
        int*   ctl  = (int*)(hb + 26112);        // [0]=scnt [1]=ticket

        const float R2 = (float)(0.2 * 0.2);
        const int OUT1 = NSAMP * 128;
        const int OUT2 = OUT1 + NSAMP * 3;
        const int OUT3 = OUT2 + NSAMP;

        while (true) {
            if (t2 == 0) ctl[1] = atomicAdd(&g_ticket, 1);
            BARH;
            const int q = ctl[1];
            if (q >= NSAMP) break;
            const int c = q & 3, m = q >> 2;
            const int row = c * MS + m;
            const int g0 = c * NPB;

            for (int i = t2; i < CAP; i += 256) cand[i] = ~0ull;
            if (t2 < 128) smax[t2] = 0;
            if (t2 == 0) {
                ctl[0] = 0;
                while (ld_acq(&g_prog[c]) <= m) __nanosleep(256);   // single poller
            }
            BARH;
            float4 ctr = __ldcg((const float4*)&g_center[row]);
            const float cx = ctr.x, cy = ctr.y, cz = ctr.z;

            // radius scan, packed pairs (exact fp32 semantics)
            {
                const u64* px2 = (const u64*)(g_px + g0);
                const u64* py2 = (const u64*)(g_py + g0);
                const u64* pz2 = (const u64*)(g_pz + g0);
                const u64 ncx2 = pk2(-cx, -cx), ncy2 = pk2(-cy, -cy), ncz2 = pk2(-cz, -cz);
                for (int iq = t2; iq < NPB / 2; iq += 256) {
                    u64 dx2 = add2(px2[iq], ncx2);
                    u64 dy2 = add2(py2[iq], ncy2);
                    u64 dz2 = add2(pz2[iq], ncz2);
                    u64 d22 = add2(add2(mul2(dx2, dx2), mul2(dy2, dy2)), mul2(dz2, dz2));
                    float d0, d1; upk2(d22, d0, d1);
                    if (d0 <= R2) {
                        int sp = atomicAdd(ctl, 1);
                        if (sp < CAP) cand[sp] = ((u64)__float_as_uint(d0) << 32) | (unsigned)(2 * iq);
                    }
                    if (d1 <= R2) {
                        int sp = atomicAdd(ctl, 1);
                        if (sp < CAP) cand[sp] = ((u64)__float_as_uint(d1) << 32) | (unsigned)(2 * iq + 1);
                    }
                }
            }
            BARH;
            int n = ctl[0]; if (n > CAP) n = CAP;

            // bitonic sort over next-pow2(n) (u64 keys: d2 major, idx minor == lax.top_k ties)
            if (n > KNB) {
                int np2 = 128;
                while (np2 < n) np2 <<= 1;
                for (int k = 2; k <= np2; k <<= 1) {
                    for (int j = k >> 1; j > 0; j >>= 1) {
                        BARH;
                        for (int i = t2; i < np2; i += 256) {
                            int ixj = i ^ j;
                            if (ixj > i) {
                                u64 a = cand[i], cc2 = cand[ixj];
                                bool asc = ((i & k) == 0);
                                if ((a > cc2) == asc) { cand[i] = cc2; cand[ixj] = a; }
                            }
                        }
                    }
                }
            }
            BARH;
            const int nv = n < KNB ? n : KNB;

            // h1 = relu(X'[j] + relpos @ W1p + b1), transposed [col][n], stride 68
            for (int p = t2; p < 4096; p += 256) {
                int nn = p >> 6, ccol = p & 63;
                float v = 0.f;
                if (nn < nv) {
                    int j = (int)(unsigned)(cand[nn] & 0xffffffffull);
                    float rx = g_px[g0 + j] - cx;
                    float ry = g_py[g0 + j] - cy;
                    float rz = g_pz[g0 + j] - cz;
                    v = g_xw1[(size_t)(g0 + j) * 64 + ccol];
                    v = fmaf(rx, W1ps[ccol], v);
                    v = fmaf(ry, W1ps[64 + ccol], v);
                    v = fmaf(rz, W1ps[128 + ccol], v);
                    v = fmaxf(v + b1s[ccol], 0.f);
                }
                h1T[ccol * 68 + nn] = v;
            }
            BARH;

            // layer 2: h2 = relu(h1 @ W2 + b2); packed f32x2
            {
                int tn = t2 >> 4, tc = t2 & 15;
                ulonglong2 bb = *(const ulonglong2*)(b2s + tc * 4);
                u64 acc[4][2];
                #pragma unroll
                for (int i = 0; i < 4; i++) { acc[i][0] = bb.x; acc[i][1] = bb.y; }
                #pragma unroll 8
                for (int k = 0; k < 64; k++) {
                    float4 a = *(const float4*)(h1T + k * 68 + tn * 4);
                    ulonglong2 ww = *(const ulonglong2*)(W2s + k * 64 + tc * 4);
                    u64 a0 = pk2(a.x, a.x), a1 = pk2(a.y, a.y), a2 = pk2(a.z, a.z), a3 = pk2(a.w, a.w);
                    acc[0][0] = fma2(a0, ww.x, acc[0][0]); acc[0][1] = fma2(a0, ww.y, acc[0][1]);
                    acc[1][0] = fma2(a1, ww.x, acc[1][0]); acc[1][1] = fma2(a1, ww.y, acc[1][1]);
                    acc[2][0] = fma2(a2, ww.x, acc[2][0]); acc[2][1] = fma2(a2, ww.y, acc[2][1]);
                    acc[3][0] = fma2(a3, ww.x, acc[3][0]); acc[3][1] = fma2(a3, ww.y, acc[3][1]);
                }
                BARH;  // all reads of h1T done; reuse buffer for h2T
                #pragma unroll
                for (int i = 0; i < 4; i++)
                    #pragma unroll
                    for (int jp = 0; jp < 2; jp++) {
                        float f0, f1; relu2(acc[i][jp], f0, f1);
                        h1T[(tc * 4 + 2 * jp) * 68 + tn * 4 + i] = f0;
                        h1T[(tc * 4 + 2 * jp + 1) * 68 + tn * 4 + i] = f1;
                    }
                BARH;
            }

            // layer 3: relu(h2 @ W3 + b3) fused with maxpool
            {
                int tn = t2 >> 4, tc = t2 & 15;
                ulonglong2 bb0 = *(const ulonglong2*)(b3s + tc * 8);
                ulonglong2 bb1 = *(const ulonglong2*)(b3s + tc * 8 + 4);
                u64 acc[4][4];
                #pragma unroll
                for (int i = 0; i < 4; i++) {
                    acc[i][0] = bb0.x; acc[i][1] = bb0.y; acc[i][2] = bb1.x; acc[i][3] = bb1.y;
                }
                #pragma unroll 4
                for (int k = 0; k < 64; k++) {
                    float4 a = *(const float4*)(h1T + k * 68 + tn * 4);
                    ulonglong2 w0 = *(const ulonglong2*)(W3s + k * 128 + tc * 8);
                    ulonglong2 w1 = *(const ulonglong2*)(W3s + k * 128 + tc * 8 + 4);
                    u64 a0 = pk2(a.x, a.x), a1 = pk2(a.y, a.y), a2 = pk2(a.z, a.z), a3 = pk2(a.w, a.w);
                    acc[0][0] = fma2(a0, w0.x, acc[0][0]); acc[0][1] = fma2(a0, w0.y, acc[0][1]);
                    acc[0][2] = fma2(a0, w1.x, acc[0][2]); acc[0][3] = fma2(a0, w1.y, acc[0][3]);
                    acc[1][0] = fma2(a1, w0.x, acc[1][0]); acc[1][1] = fma2(a1, w0.y, acc[1][1]);
                    acc[1][2] = fma2(a1, w1.x, acc[1][2]); acc[1][3] = fma2(a1, w1.y, acc[1][3]);
                    acc[2][0] = fma2(a2, w0.x, acc[2][0]); acc[2][1] = fma2(a2, w0.y, acc[2][1]);
                    acc[2][2] = fma2(a2, w1.x, acc[2][2]); acc[2][3] = fma2(a2, w1.y, acc[2][3]);
                    acc[3][0] = fma2(a3, w0.x, acc[3][0]); acc[3][1] = fma2(a3, w0.y, acc[3][1]);
                    acc[3][2] = fma2(a3, w1.x, acc[3][2]); acc[3][3] = fma2(a3, w1.y, acc[3][3]);
                }
                if (tn * 4 < nv) {
                    int vr = nv - tn * 4; if (vr > 4) vr = 4;
                    #pragma unroll
                    for (int jp = 0; jp < 4; jp++) {
                        float m0 = 0.f, m1 = 0.f;
                        for (int i = 0; i < vr; i++) {
                            float f0, f1; relu2(acc[i][jp], f0, f1);
                            m0 = fmaxf(m0, f0); m1 = fmaxf(m1, f1);
                        }
                        atomicMax(&smax[tc * 8 + 2 * jp], __float_as_int(m0));   // nonneg: int order == float order
                        atomicMax(&smax[tc * 8 + 2 * jp + 1], __float_as_int(m1));
                    }
                }
                BARH;
            }

            // outputs: [B*M,128] feat, [B*M,3] pos, [B*M] batch
            if (t2 < 128) out[(size_t)row * 128 + t2] = __int_as_float(smax[t2]);
            if (out_size >= OUT2 && t2 == 128) {
                float* po = out + OUT1 + (size_t)row * 3;
                po[0] = cx; po[1] = cy; po[2] = cz;
            }
            if (out_size >= OUT3 && t2 == 129) out[OUT2 + row] = (float)c;
            BARH;   // protect cand/smax reset of next iteration
        }
    }
}

extern "C" void kernel_launch(void* const* d_in, const int* in_sizes, int n_in,
                              void* d_out, int out_size) {
    const float* x   = (const float*)d_in[0];
    const float* pos = (const float*)d_in[1];
    // d_in[2] = batch (implicit by layout)
    const float* W1 = (const float*)d_in[3];
    const float* b1 = (const float*)d_in[4];
    const float* W2 = (const float*)d_in[5];
    const float* b2 = (const float*)d_in[6];
    const float* W3 = (const float*)d_in[7];
    const float* b3 = (const float*)d_in[8];

    cudaFuncSetAttribute(mega_kernel, cudaFuncAttributeMaxDynamicSharedMemorySize, SMEM_TOTAL);

    reset_kernel<<<1, 32>>>();
    mega_kernel<<<BATCH + NWORK, 512, SMEM_TOTAL>>>(pos, x, W1, b1, W2, b2, W3, b3,
                                                    (float*)d_out, out_size);
}

// round 15
// speedup vs baseline: 1.8309x; 1.0269x over previous
#include <cuda_runtime.h>

#define BATCH 4
#define NPB   8192
#define MS    2048
#define KNB   64
#define NPTS  (BATCH*NPB)
#define CAP   1024
#define NWORK 144
#define NSAMP (BATCH*MS)

typedef unsigned long long u64;

__device__ float  g_xw1[NPTS * 64];      // x @ W1[:64,:]
__device__ float  g_px[NPTS], g_py[NPTS], g_pz[NPTS];
__device__ float4 g_center[NSAMP];
__device__ int    g_prog[BATCH * 32];    // padded: one 128B line per cloud
__device__ int    g_ready;
__device__ int    g_ticket;

// ---------- packed f32x2 helpers (bit-exact per-lane rn) ----------
__device__ __forceinline__ u64 pk2(float a, float b) {
    u64 r; asm("mov.b64 %0,{%1,%2};" : "=l"(r) : "f"(a), "f"(b)); return r;
}
__device__ __forceinline__ void upk2(u64 v, float& a, float& b) {
    asm("mov.b64 {%0,%1},%2;" : "=f"(a), "=f"(b) : "l"(v));
}
__device__ __forceinline__ u64 fma2(u64 a, u64 b, u64 c) {
    u64 d; asm("fma.rn.f32x2 %0,%1,%2,%3;" : "=l"(d) : "l"(a), "l"(b), "l"(c)); return d;
}
__device__ __forceinline__ u64 mul2(u64 a, u64 b) {
    u64 d; asm("mul.rn.f32x2 %0,%1,%2;" : "=l"(d) : "l"(a), "l"(b)); return d;
}
__device__ __forceinline__ u64 add2(u64 a, u64 b) {
    u64 d; asm("add.rn.f32x2 %0,%1,%2;" : "=l"(d) : "l"(a), "l"(b)); return d;
}
__device__ __forceinline__ void relu2(u64 a, float& f0, float& f1) {
    upk2(a, f0, f1);
    f0 = fmaxf(f0, 0.f); f1 = fmaxf(f1, 0.f);
}
// ---------- acquire/release scalar sync ----------
__device__ __forceinline__ void st_rel(int* p, int v) {
    asm volatile("st.release.gpu.global.s32 [%0],%1;" :: "l"(p), "r"(v) : "memory");
}
__device__ __forceinline__ int ld_acq(const int* p) {
    int v; asm volatile("ld.acquire.gpu.global.s32 %0,[%1];" : "=r"(v) : "l"(p) : "memory");
    return v;
}

// ---------------- smem layout (bytes) ----------------
#define SA_W2   0
#define SA_W3   16384
#define SA_W1P  49152
#define SA_B1   49920
#define SA_B2   50176
#define SA_B3   50432
#define SA_H0   50944
#define SA_HSZ  26176            // cand 8192 + h1T 17408 + smax 512 + ctl 64
// fps role:
#define FP_SP4  0                // float4[8192] packed points = 131072 B
#define FP_RED  131072           // swv [2][16] u32 + swi [2][16] int
#define SMEM_TOTAL (FP_RED + 512)   // 131584 (workers use < 103296 of it)

extern __shared__ char smem_raw[];

#define BARH asm volatile("bar.sync %0, %1;" :: "r"(1 + h), "r"(256) : "memory")

__global__ void reset_kernel() {
    int t = threadIdx.x;
    if (t < BATCH) g_prog[t * 32] = 0;
    if (t == 4) g_ready = 0;
    if (t == 5) g_ticket = 0;
}

__global__ void __launch_bounds__(512, 1) mega_kernel(
    const float* __restrict__ pos, const float* __restrict__ x,
    const float* __restrict__ W1, const float* __restrict__ b1,
    const float* __restrict__ W2, const float* __restrict__ b2,
    const float* __restrict__ W3, const float* __restrict__ b3,
    float* __restrict__ out, int out_size) {

    const int bid = blockIdx.x;
    const int tid = threadIdx.x;

    if (bid < BATCH) {
        // ======================= FPS: one SM per cloud, 16 warps =======================
        const int b = bid;
        float4* sp4 = (float4*)(smem_raw + FP_SP4);
        unsigned* swv = (unsigned*)(smem_raw + FP_RED);          // [2][16]
        int*      swi = (int*)(smem_raw + FP_RED + 128);         // [2][16]

        const float* pb = pos + (size_t)b * NPB * 3;
        for (int i = tid; i < NPB; i += 512) {
            sp4[i] = make_float4(pb[3 * i], pb[3 * i + 1], pb[3 * i + 2], 0.f);
        }
        __syncthreads();

        u64 X2[8], Y2[8], Z2[8];
        float md[16];
        #pragma unroll
        for (int g = 0; g < 8; g++) {
            int p0 = (2 * g) * 512 + tid, p1 = p0 + 512;
            float4 a = sp4[p0], c2 = sp4[p1];
            X2[g] = pk2(a.x, c2.x);
            Y2[g] = pk2(a.y, c2.y);
            Z2[g] = pk2(a.z, c2.z);
            md[2 * g] = __int_as_float(0x7f800000);
            md[2 * g + 1] = __int_as_float(0x7f800000);
        }
        float4 c0 = sp4[0];
        float sx = c0.x, sy = c0.y, sz = c0.z;
        if (tid == 0) {
            g_center[b * MS] = make_float4(sx, sy, sz, 0.f);
            st_rel(&g_prog[b * 32], 1);
        }
        const int lane = tid & 31, wid = tid >> 5;

        for (int t = 1; t < MS; t++) {
            u64 nx = pk2(-sx, -sx), ny = pk2(-sy, -sy), nz = pk2(-sz, -sz);
            float tmax = -1.0f;
            #pragma unroll
            for (int g = 0; g < 8; g++) {
                // exact XLA fp32: rn sub (add of exact negation), rn muls, ((xx+yy)+zz)
                u64 dx = add2(X2[g], nx);
                u64 dy = add2(Y2[g], ny);
                u64 dz = add2(Z2[g], nz);
                u64 d2 = add2(add2(mul2(dx, dx), mul2(dy, dy)), mul2(dz, dz));
                float d0, d1; upk2(d2, d0, d1);
                float m0 = fminf(md[2 * g], d0);     md[2 * g] = m0;
                float m1 = fminf(md[2 * g + 1], d1); md[2 * g + 1] = m1;
                tmax = fmaxf(tmax, fmaxf(m0, m1));
            }
            unsigned vb = __float_as_uint(tmax);            // md >= 0: bits monotone
            unsigned Vw = __reduce_max_sync(0xffffffffu, vb);
            // branchless first-index scan: lanes with vb < Vw match nothing -> loc stays MAX
            float Vf = __uint_as_float(Vw);
            int loc = 0x7fffffff;
            #pragma unroll
            for (int g = 7; g >= 0; g--) {
                if (md[2 * g + 1] == Vf) loc = (2 * g + 1) * 512 + tid;
                if (md[2 * g]     == Vf) loc = (2 * g) * 512 + tid;
            }
            unsigned Iw = __reduce_min_sync(0xffffffffu, (unsigned)loc);
            const int par = (t & 1) * 16;
            if (lane == 0) { swv[par + wid] = Vw; swi[par + wid] = (int)Iw; }
            __syncthreads();   // single barrier per iter; parity double-buffer bounds skew
            unsigned v  = (lane < 16) ? swv[par + lane] : 0u;
            unsigned i2 = (lane < 16) ? (unsigned)swi[par + lane] : 0x7fffffffu;
            unsigned Vg = __reduce_max_sync(0xffffffffu, v);
            unsigned Ig = __reduce_min_sync(0xffffffffu, (v == Vg) ? i2 : 0x7fffffffu);
            float4 w = sp4[Ig];                              // single LDS.128 broadcast
            sx = w.x; sy = w.y; sz = w.z;
            if (tid == 0) {
                g_center[b * MS + t] = make_float4(sx, sy, sz, 0.f);
                st_rel(&g_prog[b * 32], t + 1);
            }
        }

    } else {
        // ======================= persistent workers: 2 halves of 256 =======================
        const int w = bid - BATCH;        // 0..143
        float* W2s  = (float*)(smem_raw + SA_W2);    // holds W1 during prologue
        float* W3s  = (float*)(smem_raw + SA_W3);
        float* W1ps = (float*)(smem_raw + SA_W1P);
        float* b1s  = (float*)(smem_raw + SA_B1);
        float* b2s  = (float*)(smem_raw + SA_B2);
        float* b3s  = (float*)(smem_raw + SA_B3);

        // ---- prologue 1: SoA transpose chunk ----
        for (int p = w * 512 + tid; p < NPTS; p += NWORK * 512) {
            g_px[p] = pos[3 * p]; g_py[p] = pos[3 * p + 1]; g_pz[p] = pos[3 * p + 2];
        }
        // ---- prologue 2: xw1 chunk (W1 staged where W2 will live) ----
        for (int i = tid; i < 4096; i += 512) W2s[i] = W1[i];
        __syncthreads();
        {
            float* xs = (float*)(smem_raw + SA_H0);
            int rl = tid >> 6, cc = tid & 63;
            for (int r0 = w * 8; r0 < NPTS; r0 += NWORK * 8) {
                xs[tid] = x[(size_t)r0 * 64 + tid];
                __syncthreads();
                float acc = 0.f;
                #pragma unroll
                for (int k = 0; k < 64; k++) acc = fmaf(xs[rl * 64 + k], W2s[k * 64 + cc], acc);
                g_xw1[(size_t)(r0 + rl) * 64 + cc] = acc;
                __syncthreads();
            }
        }
        __threadfence();          // order g_px/g_xw1 before ready signal
        __syncthreads();
        if (tid == 0) atomicAdd(&g_ready, 1);

        // ---- load MLP weights ----
        for (int i = tid; i < 4096; i += 512) W2s[i] = W2[i];
        for (int i = tid; i < 8192; i += 512) W3s[i] = W3[i];
        if (tid < 192) W1ps[tid] = W1[4096 + tid];
        if (tid < 64) { b1s[tid] = b1[tid]; b2s[tid] = b2[tid]; }
        if (tid < 128) b3s[tid] = b3[tid];
        __syncthreads();
        if (tid == 0) { while (ld_acq(&g_ready) < NWORK) __nanosleep(512); }
        __syncthreads();          // all producers done; g_px/g_xw1 globally visible

        // ---- halves: ticket loop ----
        const int h  = tid >> 8;
        const int t2 = tid & 255;
        char* hb = smem_raw + SA_H0 + h * SA_HSZ;
        u64*   cand = (u64*)hb;
        float* h1T  = (float*)(hb + 8192);       // reused as h2T after layer 2
        int*   smax = (int*)(hb + 25600);
        int*   ctl  = (int*)(hb + 26112);        // [0]=scnt [1]=ticket

        const float R2 = (float)(0.2 * 0.2);
        const int OUT1 = NSAMP * 128;
        const int OUT2 = OUT1 + NSAMP * 3;
        const int OUT3 = OUT2 + NSAMP;

        while (true) {
            if (t2 == 0) ctl[1] = atomicAdd(&g_ticket, 1);
            BARH;
            const int q = ctl[1];
            if (q >= NSAMP) break;
            const int c = q & 3, m = q >> 2;
            const int row = c * MS + m;
            const int g0 = c * NPB;

            for (int i = t2; i < CAP; i += 256) cand[i] = ~0ull;
            if (t2 < 128) smax[t2] = 0;
            if (t2 == 0) {
                ctl[0] = 0;
                // adaptive-backoff single poller: sleep proportional to deficit
                int pv;
                while ((pv = ld_acq(&g_prog[c * 32])) <= m) {
                    int def = m - pv;
                    __nanosleep(def > 8 ? 4096 : (def > 2 ? 1024 : 256));
                }
            }
            BARH;
            float4 ctr = __ldcg((const float4*)&g_center[row]);
            const float cx = ctr.x, cy = ctr.y, cz = ctr.z;

            // radius scan, packed pairs (exact fp32 semantics)
            {
                const u64* px2 = (const u64*)(g_px + g0);
                const u64* py2 = (const u64*)(g_py + g0);
                const u64* pz2 = (const u64*)(g_pz + g0);
                const u64 ncx2 = pk2(-cx, -cx), ncy2 = pk2(-cy, -cy), ncz2 = pk2(-cz, -cz);
                for (int iq = t2; iq < NPB / 2; iq += 256) {
                    u64 dx2 = add2(px2[iq], ncx2);
                    u64 dy2 = add2(py2[iq], ncy2);
                    u64 dz2 = add2(pz2[iq], ncz2);
                    u64 d22 = add2(add2(mul2(dx2, dx2), mul2(dy2, dy2)), mul2(dz2, dz2));
                    float d0, d1; upk2(d22, d0, d1);
                    if (d0 <= R2) {
                        int sp = atomicAdd(ctl, 1);
                        if (sp < CAP) cand[sp] = ((u64)__float_as_uint(d0) << 32) | (unsigned)(2 * iq);
                    }
                    if (d1 <= R2) {
                        int sp = atomicAdd(ctl, 1);
                        if (sp < CAP) cand[sp] = ((u64)__float_as_uint(d1) << 32) | (unsigned)(2 * iq + 1);
                    }
                }
            }
            BARH;
            int n = ctl[0]; if (n > CAP) n = CAP;

            // bitonic sort over next-pow2(n) (u64 keys: d2 major, idx minor == lax.top_k ties)
            if (n > KNB) {
                int np2 = 128;
                while (np2 < n) np2 <<= 1;
                for (int k = 2; k <= np2; k <<= 1) {
                    for (int j = k >> 1; j > 0; j >>= 1) {
                        BARH;
                        for (int i = t2; i < np2; i += 256) {
                            int ixj = i ^ j;
                            if (ixj > i) {
                                u64 a = cand[i], cc2 = cand[ixj];
                                bool asc = ((i & k) == 0);
                                if ((a > cc2) == asc) { cand[i] = cc2; cand[ixj] = a; }
                            }
                        }
                    }
                }
            }
            BARH;
            const int nv = n < KNB ? n : KNB;

            // h1 = relu(X'[j] + relpos @ W1p + b1), transposed [col][n], stride 68
            for (int p = t2; p < 4096; p += 256) {
                int nn = p >> 6, ccol = p & 63;
                float v = 0.f;
                if (nn < nv) {
                    int j = (int)(unsigned)(cand[nn] & 0xffffffffull);
                    float rx = g_px[g0 + j] - cx;
                    float ry = g_py[g0 + j] - cy;
                    float rz = g_pz[g0 + j] - cz;
                    v = g_xw1[(size_t)(g0 + j) * 64 + ccol];
                    v = fmaf(rx, W1ps[ccol], v);
                    v = fmaf(ry, W1ps[64 + ccol], v);
                    v = fmaf(rz, W1ps[128 + ccol], v);
                    v = fmaxf(v + b1s[ccol], 0.f);
                }
                h1T[ccol * 68 + nn] = v;
            }
            BARH;

            // layer 2: h2 = relu(h1 @ W2 + b2); packed f32x2
            {
                int tn = t2 >> 4, tc = t2 & 15;
                ulonglong2 bb = *(const ulonglong2*)(b2s + tc * 4);
                u64 acc[4][2];
                #pragma unroll
                for (int i = 0; i < 4; i++) { acc[i][0] = bb.x; acc[i][1] = bb.y; }
                #pragma unroll 8
                for (int k = 0; k < 64; k++) {
                    float4 a = *(const float4*)(h1T + k * 68 + tn * 4);
                    ulonglong2 ww = *(const ulonglong2*)(W2s + k * 64 + tc * 4);
                    u64 a0 = pk2(a.x, a.x), a1 = pk2(a.y, a.y), a2 = pk2(a.z, a.z), a3 = pk2(a.w, a.w);
                    acc[0][0] = fma2(a0, ww.x, acc[0][0]); acc[0][1] = fma2(a0, ww.y, acc[0][1]);
                    acc[1][0] = fma2(a1, ww.x, acc[1][0]); acc[1][1] = fma2(a1, ww.y, acc[1][1]);
                    acc[2][0] = fma2(a2, ww.x, acc[2][0]); acc[2][1] = fma2(a2, ww.y, acc[2][1]);
                    acc[3][0] = fma2(a3, ww.x, acc[3][0]); acc[3][1] = fma2(a3, ww.y, acc[3][1]);
                }
                BARH;  // all reads of h1T done; reuse buffer for h2T
                #pragma unroll
                for (int i = 0; i < 4; i++)
                    #pragma unroll
                    for (int jp = 0; jp < 2; jp++) {
                        float f0, f1; relu2(acc[i][jp], f0, f1);
                        h1T[(tc * 4 + 2 * jp) * 68 + tn * 4 + i] = f0;
                        h1T[(tc * 4 + 2 * jp + 1) * 68 + tn * 4 + i] = f1;
                    }
                BARH;
            }

            // layer 3: relu(h2 @ W3 + b3) fused with maxpool
            {
                int tn = t2 >> 4, tc = t2 & 15;
                ulonglong2 bb0 = *(const ulonglong2*)(b3s + tc * 8);
                ulonglong2 bb1 = *(const ulonglong2*)(b3s + tc * 8 + 4);
                u64 acc[4][4];
                #pragma unroll
                for (int i = 0; i < 4; i++) {
                    acc[i][0] = bb0.x; acc[i][1] = bb0.y; acc[i][2] = bb1.x; acc[i][3] = bb1.y;
                }
                #pragma unroll 4
                for (int k = 0; k < 64; k++) {
                    float4 a = *(const float4*)(h1T + k * 68 + tn * 4);
                    ulonglong2 w0 = *(const ulonglong2*)(W3s + k * 128 + tc * 8);
                    ulonglong2 w1 = *(const ulonglong2*)(W3s + k * 128 + tc * 8 + 4);
                    u64 a0 = pk2(a.x, a.x), a1 = pk2(a.y, a.y), a2 = pk2(a.z, a.z), a3 = pk2(a.w, a.w);
                    acc[0][0] = fma2(a0, w0.x, acc[0][0]); acc[0][1] = fma2(a0, w0.y, acc[0][1]);
                    acc[0][2] = fma2(a0, w1.x, acc[0][2]); acc[0][3] = fma2(a0, w1.y, acc[0][3]);
                    acc[1][0] = fma2(a1, w0.x, acc[1][0]); acc[1][1] = fma2(a1, w0.y, acc[1][1]);
                    acc[1][2] = fma2(a1, w1.x, acc[1][2]); acc[1][3] = fma2(a1, w1.y, acc[1][3]);
                    acc[2][0] = fma2(a2, w0.x, acc[2][0]); acc[2][1] = fma2(a2, w0.y, acc[2][1]);
                    acc[2][2] = fma2(a2, w1.x, acc[2][2]); acc[2][3] = fma2(a2, w1.y, acc[2][3]);
                    acc[3][0] = fma2(a3, w0.x, acc[3][0]); acc[3][1] = fma2(a3, w0.y, acc[3][1]);
                    acc[3][2] = fma2(a3, w1.x, acc[3][2]); acc[3][3] = fma2(a3, w1.y, acc[3][3]);
                }
                if (tn * 4 < nv) {
                    int vr = nv - tn * 4; if (vr > 4) vr = 4;
                    #pragma unroll
                    for (int jp = 0; jp < 4; jp++) {
                        float m0 = 0.f, m1 = 0.f;
                        for (int i = 0; i < vr; i++) {
                            float f0, f1; relu2(acc[i][jp], f0, f1);
                            m0 = fmaxf(m0, f0); m1 = fmaxf(m1, f1);
                        }
                        atomicMax(&smax[tc * 8 + 2 * jp], __float_as_int(m0));   // nonneg: int order == float order
                        atomicMax(&smax[tc * 8 + 2 * jp + 1], __float_as_int(m1));
                    }
                }
                BARH;
            }

            // outputs: [B*M,128] feat, [B*M,3] pos, [B*M] batch
            if (t2 < 128) out[(size_t)row * 128 + t2] = __int_as_float(smax[t2]);
            if (out_size >= OUT2 && t2 == 128) {
                float* po = out + OUT1 + (size_t)row * 3;
                po[0] = cx; po[1] = cy; po[2] = cz;
            }
            if (out_size >= OUT3 && t2 == 129) out[OUT2 + row] = (float)c;
            BARH;   // protect cand/smax reset of next iteration
        }
    }
}

extern "C" void kernel_launch(void* const* d_in, const int* in_sizes, int n_in,
                              void* d_out, int out_size) {
    const float* x   = (const float*)d_in[0];
    const float* pos = (const float*)d_in[1];
    // d_in[2] = batch (implicit by layout)
    const float* W1 = (const float*)d_in[3];
    const float* b1 = (const float*)d_in[4];
    const float* W2 = (const float*)d_in[5];
    const float* b2 = (const float*)d_in[6];
    const float* W3 = (const float*)d_in[7];
    const float* b3 = (const float*)d_in[8];

    cudaFuncSetAttribute(mega_kernel, cudaFuncAttributeMaxDynamicSharedMemorySize, SMEM_TOTAL);

    reset_kernel<<<1, 32>>>();
    mega_kernel<<<BATCH + NWORK, 512, SMEM_TOTAL>>>(pos, x, W1, b1, W2, b2, W3, b3,
                                                    (float*)d_out, out_size);
}